// round 1
// baseline (speedup 1.0000x reference)
#include <cuda_runtime.h>

#define CC    256
#define HEADS 64
#define HD    4
#define TT    32

// Scratch (static device globals — no allocation at run time)
__device__ __align__(16) float g_q[2785280];      // (N,C,L) per level, concat
__device__ __align__(16) float g_k[2850816];      // (n,h,m,4) per level, concat
__device__ __align__(16) float g_v[2850816];
__device__ __align__(16) float g_attn[2785280];   // (N,C,L)
__device__ float g_pooled[4 * 2 * CC];

__constant__ int c_L[4]     = {4096, 1024, 256, 64};
__constant__ int c_kvoff[4] = {0, 2113536, 2654208, 2801664};

__global__ void zero_ds(float* p) { p[threadIdx.x] = 0.f; }

// ---------------- pooled = mean over H*W of ds ----------------
__global__ void pooled_kernel(const float* __restrict__ d0, const float* __restrict__ d1,
                              const float* __restrict__ d2, const float* __restrict__ d3) {
    __shared__ float red[256];
    int lvl = blockIdx.z, n = blockIdx.y, c = blockIdx.x;
    const float* dp = (lvl == 0) ? d0 : (lvl == 1) ? d1 : (lvl == 2) ? d2 : d3;
    int L = c_L[lvl];
    const float* p = dp + (size_t)(n * CC + c) * L;
    float s = 0.f;
    for (int i = threadIdx.x; i < L; i += blockDim.x) s += p[i];
    red[threadIdx.x] = s;
    __syncthreads();
    for (int st = blockDim.x >> 1; st > 0; st >>= 1) {
        if (threadIdx.x < st) red[threadIdx.x] += red[threadIdx.x + st];
        __syncthreads();
    }
    if (threadIdx.x == 0) g_pooled[(lvl * 2 + n) * CC + c] = red[0] / (float)L;
}

// ---------------- ds token projections -> tail of k/v ----------------
// grid (1024, 2, 8), block 256 (8 warps, one output each)
__global__ void token_kernel(const float* __restrict__ Wdsk, const float* __restrict__ bdsk,
                             const float* __restrict__ Wdsv, const float* __restrict__ bdsv,
                             const float* __restrict__ gate) {
    int kind = blockIdx.y;                 // 0 = key, 1 = val
    int lvl = blockIdx.z >> 1, n = blockIdx.z & 1;
    int warp = threadIdx.x >> 5, lane = threadIdx.x & 31;
    int j = blockIdx.x * 8 + warp;         // 0..8191
    const float* Wr = (kind ? Wdsv : Wdsk) + (size_t)(lvl * 8192 + j) * 256;
    const float* pl = g_pooled + (lvl * 2 + n) * CC;
    float s = 0.f;
#pragma unroll
    for (int c = lane; c < 256; c += 32) s += Wr[c] * pl[c];
#pragma unroll
    for (int off = 16; off > 0; off >>= 1) s += __shfl_down_sync(0xffffffffu, s, off);
    if (lane == 0) {
        s += (kind ? bdsv : bdsk)[lvl * 8192 + j];
        if (kind) s *= 1.0f / (1.0f + __expf(-gate[lvl]));
        int h = j >> 7, d = (j >> 5) & 3, t = j & 31;
        int L = c_L[lvl], M = L + TT;
        size_t idx = (size_t)c_kvoff[lvl] + ((size_t)((n * HEADS + h) * M) + (L + t)) * HD + d;
        if (kind) g_v[idx] = s; else g_k[idx] = s;
    }
}

// ---------------- 256-K GEMM: OUT = W(256x256) @ X(256xL) + bias ----------------
// outsel: 0 -> g_q (N,C,L); 1 -> g_k (n,h,m,4); 2 -> g_v (n,h,m,4);
//         3 -> dext (residual add from res), X read from g_attn+xoff
__global__ void gemm256(const float* __restrict__ W, const float* __restrict__ bias,
                        const float* __restrict__ Xext, const float* __restrict__ res,
                        float* __restrict__ dext,
                        int L, int M, int off, int xoff, int outsel) {
    __shared__ float As[16][68];
    __shared__ float Bs[16][68];
    int n = blockIdx.z;
    int o0 = blockIdx.y * 64, l0 = blockIdx.x * 64;
    const float* X = (outsel == 3) ? (g_attn + xoff + (size_t)n * CC * L)
                                   : (Xext + (size_t)n * CC * L);
    int tx = threadIdx.x, ty = threadIdx.y;
    int t = ty * 16 + tx;
    float acc[4][4];
#pragma unroll
    for (int i = 0; i < 4; i++)
#pragma unroll
        for (int j = 0; j < 4; j++) acc[i][j] = 0.f;

    for (int k0 = 0; k0 < 256; k0 += 16) {
#pragma unroll
        for (int r = 0; r < 4; r++) {
            int idx = t + r * 256;
            As[idx & 15][idx >> 4] = W[(size_t)(o0 + (idx >> 4)) * 256 + k0 + (idx & 15)];
        }
#pragma unroll
        for (int r = 0; r < 4; r++) {
            int idx = t + r * 256;
            Bs[idx >> 6][idx & 63] = X[(size_t)(k0 + (idx >> 6)) * L + l0 + (idx & 63)];
        }
        __syncthreads();
#pragma unroll
        for (int kk = 0; kk < 16; kk++) {
            float a0 = As[kk][ty * 4], a1 = As[kk][ty * 4 + 1];
            float a2 = As[kk][ty * 4 + 2], a3 = As[kk][ty * 4 + 3];
            float b0 = Bs[kk][tx * 4], b1 = Bs[kk][tx * 4 + 1];
            float b2 = Bs[kk][tx * 4 + 2], b3 = Bs[kk][tx * 4 + 3];
            acc[0][0] += a0 * b0; acc[0][1] += a0 * b1; acc[0][2] += a0 * b2; acc[0][3] += a0 * b3;
            acc[1][0] += a1 * b0; acc[1][1] += a1 * b1; acc[1][2] += a1 * b2; acc[1][3] += a1 * b3;
            acc[2][0] += a2 * b0; acc[2][1] += a2 * b1; acc[2][2] += a2 * b2; acc[2][3] += a2 * b3;
            acc[3][0] += a3 * b0; acc[3][1] += a3 * b1; acc[3][2] += a3 * b2; acc[3][3] += a3 * b3;
        }
        __syncthreads();
    }
#pragma unroll
    for (int i = 0; i < 4; i++) {
        int o = o0 + ty * 4 + i;
        float bv = bias[o];
#pragma unroll
        for (int j = 0; j < 4; j++) {
            int l = l0 + tx * 4 + j;
            float v = acc[i][j] + bv;
            if (outsel == 0)
                g_q[off + (size_t)(n * CC + o) * L + l] = v;
            else if (outsel == 1)
                g_k[off + ((size_t)((n * HEADS + (o >> 2)) * M) + l) * HD + (o & 3)] = v;
            else if (outsel == 2)
                g_v[off + ((size_t)((n * HEADS + (o >> 2)) * M) + l) * HD + (o & 3)] = v;
            else
                dext[off + (size_t)(n * CC + o) * L + l] = v + res[(size_t)(n * CC + o) * L + l];
        }
    }
}

// ---------------- fused streaming attention (softmax + out + ds ratio) ----------------
// One thread per query. k/v tiles staged in smem as float4 per position.
__global__ void attn_kernel(int qoff, int kvoff, int L, int M,
                            float* __restrict__ dsout, float inv_hl, int lvl) {
    __shared__ float4 sk[256];
    __shared__ float4 sv[256];
    __shared__ float red[256];
    int n = blockIdx.z, h = blockIdx.y;
    int l = blockIdx.x * blockDim.x + threadIdx.x;
    size_t qb = (size_t)qoff + (size_t)(n * CC + h * HD) * L + l;
    float q0 = g_q[qb] * 0.5f;
    float q1 = g_q[qb + (size_t)L] * 0.5f;
    float q2 = g_q[qb + 2 * (size_t)L] * 0.5f;
    float q3 = g_q[qb + 3 * (size_t)L] * 0.5f;
    const float4* kp = reinterpret_cast<const float4*>(g_k) + (kvoff >> 2) + (size_t)(n * HEADS + h) * M;
    const float4* vp = reinterpret_cast<const float4*>(g_v) + (kvoff >> 2) + (size_t)(n * HEADS + h) * M;
    float n0 = 0, n1 = 0, n2 = 0, n3 = 0, den = 0, dssum = 0;

    for (int m0 = 0; m0 < M; m0 += 256) {
        int cnt = min(256, M - m0);
        for (int i = threadIdx.x; i < cnt; i += blockDim.x) {
            sk[i] = kp[m0 + i];
            sv[i] = vp[m0 + i];
        }
        __syncthreads();
        int tokstart = L - m0;
        if (tokstart > cnt) tokstart = cnt;
        if (tokstart < 0) tokstart = 0;
#pragma unroll 4
        for (int i = 0; i < tokstart; i++) {
            float4 kk = sk[i];
            float w = __expf(fmaf(q3, kk.w, fmaf(q2, kk.z, fmaf(q1, kk.y, q0 * kk.x))));
            float4 vv = sv[i];
            n0 += w * vv.x; n1 += w * vv.y; n2 += w * vv.z; n3 += w * vv.w;
            den += w;
        }
        for (int i = tokstart; i < cnt; i++) {
            float4 kk = sk[i];
            float w = __expf(fmaf(q3, kk.w, fmaf(q2, kk.z, fmaf(q1, kk.y, q0 * kk.x))));
            float4 vv = sv[i];
            n0 += w * vv.x; n1 += w * vv.y; n2 += w * vv.z; n3 += w * vv.w;
            den += w;
            dssum += w;
        }
        __syncthreads();
    }
    float r = 1.0f / den;   // ref clips softmax total at 1e-6; ratio identical (scale cancels)
    g_attn[qb] = n0 * r;
    g_attn[qb + (size_t)L] = n1 * r;
    g_attn[qb + 2 * (size_t)L] = n2 * r;
    g_attn[qb + 3 * (size_t)L] = n3 * r;
    red[threadIdx.x] = dssum * r;
    __syncthreads();
    for (int st = blockDim.x >> 1; st > 0; st >>= 1) {
        if (threadIdx.x < st) red[threadIdx.x] += red[threadIdx.x + st];
        __syncthreads();
    }
    if (threadIdx.x == 0) atomicAdd(&dsout[lvl * 2 + n], red[0] * inv_hl);
}

// ---------------- launch ----------------
extern "C" void kernel_launch(void* const* d_in, const int* in_sizes, int n_in,
                              void* d_out, int out_size) {
    const float* sp[4]; const float* iv[4]; const float* dd[4];
    for (int i = 0; i < 4; i++) {
        sp[i] = (const float*)d_in[i];
        iv[i] = (const float*)d_in[4 + i];
        dd[i] = (const float*)d_in[8 + i];
    }
    const float* Wq  = (const float*)d_in[12]; const float* bq  = (const float*)d_in[13];
    const float* Wk  = (const float*)d_in[14]; const float* bk  = (const float*)d_in[15];
    const float* Wv  = (const float*)d_in[16]; const float* bv  = (const float*)d_in[17];
    const float* Wo  = (const float*)d_in[18]; const float* bo  = (const float*)d_in[19];
    const float* Wdsk = (const float*)d_in[20]; const float* bdsk = (const float*)d_in[21];
    const float* Wdsv = (const float*)d_in[22]; const float* bdsv = (const float*)d_in[23];
    const float* gate = (const float*)d_in[24];
    float* out = (float*)d_out;

    static const int Lt[4]    = {4096, 1024, 256, 64};
    static const int qoff[4]  = {0, 2097152, 2621440, 2752512};
    static const int kvoff[4] = {0, 2113536, 2654208, 2801664};
    float* dsout = out + (out_size - 8);

    zero_ds<<<1, 8>>>(dsout);
    pooled_kernel<<<dim3(256, 2, 4), 256>>>(dd[0], dd[1], dd[2], dd[3]);
    token_kernel<<<dim3(1024, 2, 8), 256>>>(Wdsk, bdsk, Wdsv, bdsv, gate);

    for (int lv = 0; lv < 4; lv++) {
        int L = Lt[lv], M = L + 32;
        dim3 grid(L / 64, 4, 2), blk(16, 16);
        gemm256<<<grid, blk>>>(Wq + lv * 65536, bq + lv * 256, sp[lv], nullptr, nullptr,
                               L, M, qoff[lv], 0, 0);
        gemm256<<<grid, blk>>>(Wk + lv * 65536, bk + lv * 256, iv[lv], nullptr, nullptr,
                               L, M, kvoff[lv], 0, 1);
        gemm256<<<grid, blk>>>(Wv + lv * 65536, bv + lv * 256, iv[lv], nullptr, nullptr,
                               L, M, kvoff[lv], 0, 2);
    }
    for (int lv = 0; lv < 4; lv++) {
        int L = Lt[lv], M = L + 32;
        int bt = (L < 256) ? L : 256;
        attn_kernel<<<dim3(L / bt, HEADS, 2), bt>>>(qoff[lv], kvoff[lv], L, M,
                                                    dsout, 1.0f / (64.0f * (float)L), lv);
    }
    for (int lv = 0; lv < 4; lv++) {
        int L = Lt[lv], M = L + 32;
        dim3 grid(L / 64, 4, 2), blk(16, 16);
        gemm256<<<grid, blk>>>(Wo + lv * 65536, bo + lv * 256, nullptr, sp[lv], out,
                               L, M, qoff[lv], qoff[lv], 3);
    }
}

// round 2
// speedup vs baseline: 1.0731x; 1.0731x over previous
#include <cuda_runtime.h>

#define CC    256
#define HEADS 64
#define HD    4
#define TT    32

typedef unsigned long long u64;

// Scratch (static device globals — no allocation at run time)
__device__ __align__(16) float g_q[2785280];      // (N,C,L) per level, concat
__device__ __align__(16) float g_k[2850816];      // (n,h,pair,d,2) per level, concat
__device__ __align__(16) float g_v[2850816];
__device__ __align__(16) float g_attn[2785280];   // (N,C,L)
__device__ float g_pooled[4 * 2 * CC];

__constant__ int c_L[4]     = {4096, 1024, 256, 64};
__constant__ int c_kvoff[4] = {0, 2113536, 2654208, 2801664};

// ---- packed f32x2 helpers ----
__device__ __forceinline__ u64 pk2(float a, float b) {
    u64 r; asm("mov.b64 %0,{%1,%2};" : "=l"(r) : "f"(a), "f"(b)); return r;
}
__device__ __forceinline__ void upk2(u64 v, float& a, float& b) {
    asm("mov.b64 {%0,%1},%2;" : "=f"(a), "=f"(b) : "l"(v));
}
__device__ __forceinline__ u64 fma2(u64 a, u64 b, u64 c) {
    u64 d; asm("fma.rn.f32x2 %0,%1,%2,%3;" : "=l"(d) : "l"(a), "l"(b), "l"(c)); return d;
}
__device__ __forceinline__ u64 mul2(u64 a, u64 b) {
    u64 d; asm("mul.rn.f32x2 %0,%1,%2;" : "=l"(d) : "l"(a), "l"(b)); return d;
}
__device__ __forceinline__ u64 add2(u64 a, u64 b) {
    u64 d; asm("add.rn.f32x2 %0,%1,%2;" : "=l"(d) : "l"(a), "l"(b)); return d;
}
__device__ __forceinline__ float ex2f(float x) {
    float r; asm("ex2.approx.f32 %0,%1;" : "=f"(r) : "f"(x)); return r;
}

__global__ void zero_ds(float* p) { p[threadIdx.x] = 0.f; }

// ---------------- pooled = mean over H*W of ds ----------------
__global__ void pooled_kernel(const float* __restrict__ d0, const float* __restrict__ d1,
                              const float* __restrict__ d2, const float* __restrict__ d3) {
    __shared__ float red[256];
    int lvl = blockIdx.z, n = blockIdx.y, c = blockIdx.x;
    const float* dp = (lvl == 0) ? d0 : (lvl == 1) ? d1 : (lvl == 2) ? d2 : d3;
    int L = c_L[lvl];
    const float* p = dp + (size_t)(n * CC + c) * L;
    float s = 0.f;
    for (int i = threadIdx.x; i < L; i += blockDim.x) s += p[i];
    red[threadIdx.x] = s;
    __syncthreads();
    for (int st = blockDim.x >> 1; st > 0; st >>= 1) {
        if (threadIdx.x < st) red[threadIdx.x] += red[threadIdx.x + st];
        __syncthreads();
    }
    if (threadIdx.x == 0) g_pooled[(lvl * 2 + n) * CC + c] = red[0] / (float)L;
}

// ---------------- ds token projections -> tail of k/v ----------------
__global__ void token_kernel(const float* __restrict__ Wdsk, const float* __restrict__ bdsk,
                             const float* __restrict__ Wdsv, const float* __restrict__ bdsv,
                             const float* __restrict__ gate) {
    int kind = blockIdx.y;                 // 0 = key, 1 = val
    int lvl = blockIdx.z >> 1, n = blockIdx.z & 1;
    int warp = threadIdx.x >> 5, lane = threadIdx.x & 31;
    int j = blockIdx.x * 8 + warp;         // 0..8191
    const float* Wr = (kind ? Wdsv : Wdsk) + (size_t)(lvl * 8192 + j) * 256;
    const float* pl = g_pooled + (lvl * 2 + n) * CC;
    float s = 0.f;
#pragma unroll
    for (int c = lane; c < 256; c += 32) s += Wr[c] * pl[c];
#pragma unroll
    for (int off = 16; off > 0; off >>= 1) s += __shfl_down_sync(0xffffffffu, s, off);
    if (lane == 0) {
        s += (kind ? bdsv : bdsk)[lvl * 8192 + j];
        if (kind) s *= 1.0f / (1.0f + __expf(-gate[lvl]));
        int h = j >> 7, d = (j >> 5) & 3, t = j & 31;
        int L = c_L[lvl], M = L + TT;
        int m = L + t;
        // pair layout: base + ((n*H+h)*(M/2) + m/2)*8 + d*2 + (m&1)
        size_t idx = (size_t)c_kvoff[lvl]
                   + ((size_t)((n * HEADS + h) * (M >> 1)) + (m >> 1)) * 8 + d * 2 + (m & 1);
        if (kind) g_v[idx] = s; else g_k[idx] = s;
    }
}

// ---------------- 256-K GEMM: OUT = W(256x256) @ X(256xL) + bias ----------------
__global__ void gemm256(const float* __restrict__ W, const float* __restrict__ bias,
                        const float* __restrict__ Xext, const float* __restrict__ res,
                        float* __restrict__ dext,
                        int L, int M, int off, int xoff, int outsel) {
    __shared__ float As[16][68];
    __shared__ float Bs[16][68];
    int n = blockIdx.z;
    int o0 = blockIdx.y * 64, l0 = blockIdx.x * 64;
    const float* X = (outsel == 3) ? (g_attn + xoff + (size_t)n * CC * L)
                                   : (Xext + (size_t)n * CC * L);
    int tx = threadIdx.x, ty = threadIdx.y;
    int t = ty * 16 + tx;
    float acc[4][4];
#pragma unroll
    for (int i = 0; i < 4; i++)
#pragma unroll
        for (int j = 0; j < 4; j++) acc[i][j] = 0.f;

    for (int k0 = 0; k0 < 256; k0 += 16) {
#pragma unroll
        for (int r = 0; r < 4; r++) {
            int idx = t + r * 256;
            As[idx & 15][idx >> 4] = W[(size_t)(o0 + (idx >> 4)) * 256 + k0 + (idx & 15)];
        }
#pragma unroll
        for (int r = 0; r < 4; r++) {
            int idx = t + r * 256;
            Bs[idx >> 6][idx & 63] = X[(size_t)(k0 + (idx >> 6)) * L + l0 + (idx & 63)];
        }
        __syncthreads();
#pragma unroll
        for (int kk = 0; kk < 16; kk++) {
            float a0 = As[kk][ty * 4], a1 = As[kk][ty * 4 + 1];
            float a2 = As[kk][ty * 4 + 2], a3 = As[kk][ty * 4 + 3];
            float b0 = Bs[kk][tx * 4], b1 = Bs[kk][tx * 4 + 1];
            float b2 = Bs[kk][tx * 4 + 2], b3 = Bs[kk][tx * 4 + 3];
            acc[0][0] += a0 * b0; acc[0][1] += a0 * b1; acc[0][2] += a0 * b2; acc[0][3] += a0 * b3;
            acc[1][0] += a1 * b0; acc[1][1] += a1 * b1; acc[1][2] += a1 * b2; acc[1][3] += a1 * b3;
            acc[2][0] += a2 * b0; acc[2][1] += a2 * b1; acc[2][2] += a2 * b2; acc[2][3] += a2 * b3;
            acc[3][0] += a3 * b0; acc[3][1] += a3 * b1; acc[3][2] += a3 * b2; acc[3][3] += a3 * b3;
        }
        __syncthreads();
    }
#pragma unroll
    for (int i = 0; i < 4; i++) {
        int o = o0 + ty * 4 + i;
        float bv = bias[o];
#pragma unroll
        for (int j = 0; j < 4; j++) {
            int l = l0 + tx * 4 + j;
            float v = acc[i][j] + bv;
            if (outsel == 0)
                g_q[off + (size_t)(n * CC + o) * L + l] = v;
            else if (outsel == 1 || outsel == 2) {
                int h = o >> 2, d = o & 3;
                size_t idx = (size_t)off
                           + ((size_t)((n * HEADS + h) * (M >> 1)) + (l >> 1)) * 8 + d * 2 + (l & 1);
                if (outsel == 1) g_k[idx] = v; else g_v[idx] = v;
            } else
                dext[off + (size_t)(n * CC + o) * L + l] = v + res[(size_t)(n * CC + o) * L + l];
        }
    }
}

// ---------------- fused streaming attention (packed f32x2, 2 keys/iter) ----------------
// One thread per query. kv tiles staged in smem; each key position = 16 bytes,
// pair layout gives (d0,d1 | d2,d3) x (m, m+1) per two consecutive 16B chunks.
__global__ void attn_kernel(int qoff, int kvoff, int L, int M,
                            float* __restrict__ dsout, float inv_hl, int lvl) {
    __shared__ ulonglong2 sk[256];
    __shared__ ulonglong2 sv[256];
    __shared__ float red[256];
    int n = blockIdx.z, h = blockIdx.y;
    int l = blockIdx.x * blockDim.x + threadIdx.x;
    const float SC = 0.5f * 1.4426950408889634f;   // scale * log2(e), folded into q
    size_t qb = (size_t)qoff + (size_t)(n * CC + h * HD) * L + l;
    u64 q0 = pk2(g_q[qb] * SC, g_q[qb] * SC);
    float t1 = g_q[qb + (size_t)L] * SC;            u64 q1 = pk2(t1, t1);
    float t2 = g_q[qb + 2 * (size_t)L] * SC;        u64 q2 = pk2(t2, t2);
    float t3 = g_q[qb + 3 * (size_t)L] * SC;        u64 q3 = pk2(t3, t3);
    const ulonglong2* kp = reinterpret_cast<const ulonglong2*>(g_k) + (kvoff >> 2)
                         + (size_t)(n * HEADS + h) * M;
    const ulonglong2* vp = reinterpret_cast<const ulonglong2*>(g_v) + (kvoff >> 2)
                         + (size_t)(n * HEADS + h) * M;
    u64 A0 = 0, A1 = 0, A2 = 0, A3 = 0, den2 = 0, ds2 = 0;

    for (int m0 = 0; m0 < M; m0 += 256) {
        int cnt = min(256, M - m0);
        for (int i = threadIdx.x; i < cnt; i += blockDim.x) {
            sk[i] = kp[m0 + i];
            sv[i] = vp[m0 + i];
        }
        __syncthreads();
        int ts = L - m0;
        if (ts > cnt) ts = cnt;
        if (ts < 0) ts = 0;
        int tp = ts >> 1, np = cnt >> 1;
#pragma unroll 4
        for (int p = 0; p < tp; p++) {
            ulonglong2 ka = sk[2 * p], kb = sk[2 * p + 1];
            u64 lg = fma2(q3, kb.y, fma2(q2, kb.x, fma2(q1, ka.y, mul2(q0, ka.x))));
            float x0, x1; upk2(lg, x0, x1);
            u64 w = pk2(ex2f(x0), ex2f(x1));
            ulonglong2 va = sv[2 * p], vb = sv[2 * p + 1];
            A0 = fma2(w, va.x, A0); A1 = fma2(w, va.y, A1);
            A2 = fma2(w, vb.x, A2); A3 = fma2(w, vb.y, A3);
            den2 = add2(den2, w);
        }
#pragma unroll 2
        for (int p = tp; p < np; p++) {
            ulonglong2 ka = sk[2 * p], kb = sk[2 * p + 1];
            u64 lg = fma2(q3, kb.y, fma2(q2, kb.x, fma2(q1, ka.y, mul2(q0, ka.x))));
            float x0, x1; upk2(lg, x0, x1);
            u64 w = pk2(ex2f(x0), ex2f(x1));
            ulonglong2 va = sv[2 * p], vb = sv[2 * p + 1];
            A0 = fma2(w, va.x, A0); A1 = fma2(w, va.y, A1);
            A2 = fma2(w, vb.x, A2); A3 = fma2(w, vb.y, A3);
            den2 = add2(den2, w);
            ds2 = add2(ds2, w);
        }
        __syncthreads();
    }
    float dl, dh; upk2(den2, dl, dh);
    float r = 1.0f / (dl + dh);   // ref clips total at 1e-6; ratio identical (scale cancels)
    float a, b;
    upk2(A0, a, b); g_attn[qb] = (a + b) * r;
    upk2(A1, a, b); g_attn[qb + (size_t)L] = (a + b) * r;
    upk2(A2, a, b); g_attn[qb + 2 * (size_t)L] = (a + b) * r;
    upk2(A3, a, b); g_attn[qb + 3 * (size_t)L] = (a + b) * r;
    float sl, sh; upk2(ds2, sl, sh);
    red[threadIdx.x] = (sl + sh) * r;
    __syncthreads();
    for (int st = blockDim.x >> 1; st > 0; st >>= 1) {
        if (threadIdx.x < st) red[threadIdx.x] += red[threadIdx.x + st];
        __syncthreads();
    }
    if (threadIdx.x == 0) atomicAdd(&dsout[lvl * 2 + n], red[0] * inv_hl);
}

// ---------------- launch ----------------
extern "C" void kernel_launch(void* const* d_in, const int* in_sizes, int n_in,
                              void* d_out, int out_size) {
    const float* sp[4]; const float* iv[4]; const float* dd[4];
    for (int i = 0; i < 4; i++) {
        sp[i] = (const float*)d_in[i];
        iv[i] = (const float*)d_in[4 + i];
        dd[i] = (const float*)d_in[8 + i];
    }
    const float* Wq  = (const float*)d_in[12]; const float* bq  = (const float*)d_in[13];
    const float* Wk  = (const float*)d_in[14]; const float* bk  = (const float*)d_in[15];
    const float* Wv  = (const float*)d_in[16]; const float* bv  = (const float*)d_in[17];
    const float* Wo  = (const float*)d_in[18]; const float* bo  = (const float*)d_in[19];
    const float* Wdsk = (const float*)d_in[20]; const float* bdsk = (const float*)d_in[21];
    const float* Wdsv = (const float*)d_in[22]; const float* bdsv = (const float*)d_in[23];
    const float* gate = (const float*)d_in[24];
    float* out = (float*)d_out;

    static const int Lt[4]    = {4096, 1024, 256, 64};
    static const int qoff[4]  = {0, 2097152, 2621440, 2752512};
    static const int kvoff[4] = {0, 2113536, 2654208, 2801664};
    float* dsout = out + (out_size - 8);

    zero_ds<<<1, 8>>>(dsout);
    pooled_kernel<<<dim3(256, 2, 4), 256>>>(dd[0], dd[1], dd[2], dd[3]);
    token_kernel<<<dim3(1024, 2, 8), 256>>>(Wdsk, bdsk, Wdsv, bdsv, gate);

    for (int lv = 0; lv < 4; lv++) {
        int L = Lt[lv], M = L + 32;
        dim3 grid(L / 64, 4, 2), blk(16, 16);
        gemm256<<<grid, blk>>>(Wq + lv * 65536, bq + lv * 256, sp[lv], nullptr, nullptr,
                               L, M, qoff[lv], 0, 0);
        gemm256<<<grid, blk>>>(Wk + lv * 65536, bk + lv * 256, iv[lv], nullptr, nullptr,
                               L, M, kvoff[lv], 0, 1);
        gemm256<<<grid, blk>>>(Wv + lv * 65536, bv + lv * 256, iv[lv], nullptr, nullptr,
                               L, M, kvoff[lv], 0, 2);
    }
    for (int lv = 0; lv < 4; lv++) {
        int L = Lt[lv], M = L + 32;
        int bt = (L < 256) ? L : 256;
        attn_kernel<<<dim3(L / bt, HEADS, 2), bt>>>(qoff[lv], kvoff[lv], L, M,
                                                    dsout, 1.0f / (64.0f * (float)L), lv);
    }
    for (int lv = 0; lv < 4; lv++) {
        int L = Lt[lv], M = L + 32;
        dim3 grid(L / 64, 4, 2), blk(16, 16);
        gemm256<<<grid, blk>>>(Wo + lv * 65536, bo + lv * 256, nullptr, sp[lv], out,
                               L, M, qoff[lv], qoff[lv], 3);
    }
}

// round 3
// speedup vs baseline: 1.0776x; 1.0043x over previous
#include <cuda_runtime.h>

#define CC    256
#define HEADS 64
#define HD    4
#define TT    32

typedef unsigned long long u64;

// Scratch (static device globals — no allocation at run time)
__device__ __align__(16) float g_q[2785280];      // (N,C,L) per level, concat
__device__ __align__(16) float g_k[2850816];      // (n,h,pair,d,2) per level, concat
__device__ __align__(16) float g_v[2850816];
__device__ __align__(16) float g_attn[2785280];   // (N,C,L)
__device__ float g_pooled[4 * 2 * CC];

__constant__ int c_L[4]     = {4096, 1024, 256, 64};
__constant__ int c_kvoff[4] = {0, 2113536, 2654208, 2801664};

// ---- packed f32x2 helpers ----
__device__ __forceinline__ u64 pk2(float a, float b) {
    u64 r; asm("mov.b64 %0,{%1,%2};" : "=l"(r) : "f"(a), "f"(b)); return r;
}
__device__ __forceinline__ void upk2(u64 v, float& a, float& b) {
    asm("mov.b64 {%0,%1},%2;" : "=f"(a), "=f"(b) : "l"(v));
}
__device__ __forceinline__ u64 fma2(u64 a, u64 b, u64 c) {
    u64 d; asm("fma.rn.f32x2 %0,%1,%2,%3;" : "=l"(d) : "l"(a), "l"(b), "l"(c)); return d;
}
__device__ __forceinline__ u64 mul2(u64 a, u64 b) {
    u64 d; asm("mul.rn.f32x2 %0,%1,%2;" : "=l"(d) : "l"(a), "l"(b)); return d;
}
__device__ __forceinline__ u64 add2(u64 a, u64 b) {
    u64 d; asm("add.rn.f32x2 %0,%1,%2;" : "=l"(d) : "l"(a), "l"(b)); return d;
}
__device__ __forceinline__ float ex2f(float x) {
    float r; asm("ex2.approx.f32 %0,%1;" : "=f"(r) : "f"(x)); return r;
}

// ---------------- pooled = mean over H*W of ds (also zeroes ds output) ----------------
__global__ void pooled_kernel(const float* __restrict__ d0, const float* __restrict__ d1,
                              const float* __restrict__ d2, const float* __restrict__ d3,
                              float* __restrict__ dsout) {
    __shared__ float red[256];
    int lvl = blockIdx.z, n = blockIdx.y, c = blockIdx.x;
    if (lvl == 0 && n == 0 && c == 0 && threadIdx.x < 8) dsout[threadIdx.x] = 0.f;
    const float* dp = (lvl == 0) ? d0 : (lvl == 1) ? d1 : (lvl == 2) ? d2 : d3;
    int L = c_L[lvl];
    const float* p = dp + (size_t)(n * CC + c) * L;
    float s = 0.f;
    for (int i = threadIdx.x; i < L; i += blockDim.x) s += p[i];
    red[threadIdx.x] = s;
    __syncthreads();
    for (int st = blockDim.x >> 1; st > 0; st >>= 1) {
        if (threadIdx.x < st) red[threadIdx.x] += red[threadIdx.x + st];
        __syncthreads();
    }
    if (threadIdx.x == 0) g_pooled[(lvl * 2 + n) * CC + c] = red[0] / (float)L;
}

// ---------------- ds token projections -> tail of k/v ----------------
__global__ void token_kernel(const float* __restrict__ Wdsk, const float* __restrict__ bdsk,
                             const float* __restrict__ Wdsv, const float* __restrict__ bdsv,
                             const float* __restrict__ gate) {
    int kind = blockIdx.y;                 // 0 = key, 1 = val
    int lvl = blockIdx.z >> 1, n = blockIdx.z & 1;
    int warp = threadIdx.x >> 5, lane = threadIdx.x & 31;
    int j = blockIdx.x * 8 + warp;         // 0..8191
    const float* Wr = (kind ? Wdsv : Wdsk) + (size_t)(lvl * 8192 + j) * 256;
    const float* pl = g_pooled + (lvl * 2 + n) * CC;
    float s = 0.f;
#pragma unroll
    for (int c = lane; c < 256; c += 32) s += Wr[c] * pl[c];
#pragma unroll
    for (int off = 16; off > 0; off >>= 1) s += __shfl_down_sync(0xffffffffu, s, off);
    if (lane == 0) {
        s += (kind ? bdsv : bdsk)[lvl * 8192 + j];
        if (kind) s *= 1.0f / (1.0f + __expf(-gate[lvl]));
        int h = j >> 7, d = (j >> 5) & 3, t = j & 31;
        int L = c_L[lvl], M = L + TT;
        int m = L + t;
        // pair layout: base + ((n*H+h)*(M/2) + m/2)*8 + d*2 + (m&1)
        size_t idx = (size_t)c_kvoff[lvl]
                   + ((size_t)((n * HEADS + h) * (M >> 1)) + (m >> 1)) * 8 + d * 2 + (m & 1);
        if (kind) g_v[idx] = s; else g_k[idx] = s;
    }
}

// ---------------- 256-K GEMM: OUT = W(256x256) @ X(256xL) + bias ----------------
__global__ void gemm256(const float* __restrict__ W, const float* __restrict__ bias,
                        const float* __restrict__ Xext, const float* __restrict__ res,
                        float* __restrict__ dext,
                        int L, int M, int off, int xoff, int outsel) {
    __shared__ float As[16][68];
    __shared__ float Bs[16][68];
    int n = blockIdx.z;
    int o0 = blockIdx.y * 64, l0 = blockIdx.x * 64;
    const float* X = (outsel == 3) ? (g_attn + xoff + (size_t)n * CC * L)
                                   : (Xext + (size_t)n * CC * L);
    int tx = threadIdx.x, ty = threadIdx.y;
    int t = ty * 16 + tx;
    float acc[4][4];
#pragma unroll
    for (int i = 0; i < 4; i++)
#pragma unroll
        for (int j = 0; j < 4; j++) acc[i][j] = 0.f;

    for (int k0 = 0; k0 < 256; k0 += 16) {
#pragma unroll
        for (int r = 0; r < 4; r++) {
            int idx = t + r * 256;
            As[idx & 15][idx >> 4] = W[(size_t)(o0 + (idx >> 4)) * 256 + k0 + (idx & 15)];
        }
#pragma unroll
        for (int r = 0; r < 4; r++) {
            int idx = t + r * 256;
            Bs[idx >> 6][idx & 63] = X[(size_t)(k0 + (idx >> 6)) * L + l0 + (idx & 63)];
        }
        __syncthreads();
#pragma unroll
        for (int kk = 0; kk < 16; kk++) {
            float a0 = As[kk][ty * 4], a1 = As[kk][ty * 4 + 1];
            float a2 = As[kk][ty * 4 + 2], a3 = As[kk][ty * 4 + 3];
            float b0 = Bs[kk][tx * 4], b1 = Bs[kk][tx * 4 + 1];
            float b2 = Bs[kk][tx * 4 + 2], b3 = Bs[kk][tx * 4 + 3];
            acc[0][0] += a0 * b0; acc[0][1] += a0 * b1; acc[0][2] += a0 * b2; acc[0][3] += a0 * b3;
            acc[1][0] += a1 * b0; acc[1][1] += a1 * b1; acc[1][2] += a1 * b2; acc[1][3] += a1 * b3;
            acc[2][0] += a2 * b0; acc[2][1] += a2 * b1; acc[2][2] += a2 * b2; acc[2][3] += a2 * b3;
            acc[3][0] += a3 * b0; acc[3][1] += a3 * b1; acc[3][2] += a3 * b2; acc[3][3] += a3 * b3;
        }
        __syncthreads();
    }
#pragma unroll
    for (int i = 0; i < 4; i++) {
        int o = o0 + ty * 4 + i;
        float bv = bias[o];
#pragma unroll
        for (int j = 0; j < 4; j++) {
            int l = l0 + tx * 4 + j;
            float v = acc[i][j] + bv;
            if (outsel == 0)
                g_q[off + (size_t)(n * CC + o) * L + l] = v;
            else if (outsel == 1 || outsel == 2) {
                int h = o >> 2, d = o & 3;
                size_t idx = (size_t)off
                           + ((size_t)((n * HEADS + h) * (M >> 1)) + (l >> 1)) * 8 + d * 2 + (l & 1);
                if (outsel == 1) g_k[idx] = v; else g_v[idx] = v;
            } else
                dext[off + (size_t)(n * CC + o) * L + l] = v + res[(size_t)(n * CC + o) * L + l];
        }
    }
}

// ---------------- fused streaming attention (packed f32x2, double-buffered KV) ----------------
// One thread per query, block = 256 threads. KV tiles of 256 keys are
// register-prefetched one tile ahead and staged through alternating smem buffers.
__global__ void __launch_bounds__(256) attn_kernel(int qoff, int kvoff, int L, int M,
                                                   float* __restrict__ dsout,
                                                   float inv_hl, int lvl) {
    __shared__ ulonglong2 sk[2][256];
    __shared__ ulonglong2 sv[2][256];
    __shared__ float red[8];
    int n = blockIdx.z, h = blockIdx.y;
    int lraw = blockIdx.x * 256 + threadIdx.x;
    int l = (lraw < L) ? lraw : (L - 1);
    const float SC = 0.5f * 1.4426950408889634f;   // scale * log2(e), folded into q
    size_t qb = (size_t)qoff + (size_t)(n * CC + h * HD) * L + l;
    float t0 = g_q[qb] * SC;                 u64 q0 = pk2(t0, t0);
    float t1 = g_q[qb + (size_t)L] * SC;     u64 q1 = pk2(t1, t1);
    float t2 = g_q[qb + 2 * (size_t)L] * SC; u64 q2 = pk2(t2, t2);
    float t3 = g_q[qb + 3 * (size_t)L] * SC; u64 q3 = pk2(t3, t3);
    const ulonglong2* kp = reinterpret_cast<const ulonglong2*>(g_k) + (kvoff >> 2)
                         + (size_t)(n * HEADS + h) * M;
    const ulonglong2* vp = reinterpret_cast<const ulonglong2*>(g_v) + (kvoff >> 2)
                         + (size_t)(n * HEADS + h) * M;
    u64 A0 = 0, A1 = 0, A2 = 0, A3 = 0, den2 = 0, ds2 = 0;

    int tiles = (M + 255) >> 8;
    // prologue: fetch tile 0 and stage it in buffer 0
    ulonglong2 rk = make_ulonglong2(0, 0), rv = make_ulonglong2(0, 0);
    if ((int)threadIdx.x < M) { rk = kp[threadIdx.x]; rv = vp[threadIdx.x]; }
    if ((int)threadIdx.x < min(256, M)) { sk[0][threadIdx.x] = rk; sv[0][threadIdx.x] = rv; }
    __syncthreads();

    int buf = 0;
    for (int t = 0; t < tiles; t++) {
        int base = t * 256;
        int cnt = min(256, M - base);
        // prefetch next tile into registers (latency overlapped with compute below)
        int nbase = base + 256;
        bool pf = (nbase < M) && ((int)threadIdx.x < (M - nbase));
        if (pf) { rk = kp[nbase + threadIdx.x]; rv = vp[nbase + threadIdx.x]; }

        const ulonglong2* skb = sk[buf];
        const ulonglong2* svb = sv[buf];
        int ts = L - base;
        if (ts > cnt) ts = cnt;
        if (ts < 0) ts = 0;
        int tp = ts >> 1, np = cnt >> 1;
#pragma unroll 4
        for (int p = 0; p < tp; p++) {
            ulonglong2 ka = skb[2 * p], kb = skb[2 * p + 1];
            u64 lg = fma2(q3, kb.y, fma2(q2, kb.x, fma2(q1, ka.y, mul2(q0, ka.x))));
            float x0, x1; upk2(lg, x0, x1);
            u64 w = pk2(ex2f(x0), ex2f(x1));
            ulonglong2 va = svb[2 * p], vb = svb[2 * p + 1];
            A0 = fma2(w, va.x, A0); A1 = fma2(w, va.y, A1);
            A2 = fma2(w, vb.x, A2); A3 = fma2(w, vb.y, A3);
            den2 = add2(den2, w);
        }
#pragma unroll 2
        for (int p = tp; p < np; p++) {
            ulonglong2 ka = skb[2 * p], kb = skb[2 * p + 1];
            u64 lg = fma2(q3, kb.y, fma2(q2, kb.x, fma2(q1, ka.y, mul2(q0, ka.x))));
            float x0, x1; upk2(lg, x0, x1);
            u64 w = pk2(ex2f(x0), ex2f(x1));
            ulonglong2 va = svb[2 * p], vb = svb[2 * p + 1];
            A0 = fma2(w, va.x, A0); A1 = fma2(w, va.y, A1);
            A2 = fma2(w, vb.x, A2); A3 = fma2(w, vb.y, A3);
            den2 = add2(den2, w);
            ds2 = add2(ds2, w);
        }
        // stage prefetched tile into the other buffer (no conflict with reads of buf)
        if (pf) { sk[buf ^ 1][threadIdx.x] = rk; sv[buf ^ 1][threadIdx.x] = rv; }
        __syncthreads();
        buf ^= 1;
    }

    float dl, dh; upk2(den2, dl, dh);
    float r = 1.0f / (dl + dh);   // ref clips total at 1e-6; ratio identical (scale cancels)
    if (lraw < L) {
        float a, b;
        upk2(A0, a, b); g_attn[qb] = (a + b) * r;
        upk2(A1, a, b); g_attn[qb + (size_t)L] = (a + b) * r;
        upk2(A2, a, b); g_attn[qb + 2 * (size_t)L] = (a + b) * r;
        upk2(A3, a, b); g_attn[qb + 3 * (size_t)L] = (a + b) * r;
    }
    float sl, sh; upk2(ds2, sl, sh);
    float contrib = (lraw < L) ? (sl + sh) * r : 0.f;
#pragma unroll
    for (int off = 16; off > 0; off >>= 1) contrib += __shfl_down_sync(0xffffffffu, contrib, off);
    int warp = threadIdx.x >> 5, lane = threadIdx.x & 31;
    if (lane == 0) red[warp] = contrib;
    __syncthreads();
    if (threadIdx.x == 0) {
        float s = 0.f;
#pragma unroll
        for (int i = 0; i < 8; i++) s += red[i];
        atomicAdd(&dsout[lvl * 2 + n], s * inv_hl);
    }
}

// ---------------- launch ----------------
extern "C" void kernel_launch(void* const* d_in, const int* in_sizes, int n_in,
                              void* d_out, int out_size) {
    const float* sp[4]; const float* iv[4]; const float* dd[4];
    for (int i = 0; i < 4; i++) {
        sp[i] = (const float*)d_in[i];
        iv[i] = (const float*)d_in[4 + i];
        dd[i] = (const float*)d_in[8 + i];
    }
    const float* Wq  = (const float*)d_in[12]; const float* bq  = (const float*)d_in[13];
    const float* Wk  = (const float*)d_in[14]; const float* bk  = (const float*)d_in[15];
    const float* Wv  = (const float*)d_in[16]; const float* bv  = (const float*)d_in[17];
    const float* Wo  = (const float*)d_in[18]; const float* bo  = (const float*)d_in[19];
    const float* Wdsk = (const float*)d_in[20]; const float* bdsk = (const float*)d_in[21];
    const float* Wdsv = (const float*)d_in[22]; const float* bdsv = (const float*)d_in[23];
    const float* gate = (const float*)d_in[24];
    float* out = (float*)d_out;

    static const int Lt[4]    = {4096, 1024, 256, 64};
    static const int qoff[4]  = {0, 2097152, 2621440, 2752512};
    static const int kvoff[4] = {0, 2113536, 2654208, 2801664};
    float* dsout = out + (out_size - 8);

    // Launch order puts attn(level 0) at launch index 5 so ncu (-s 5 -c 1) profiles it.
    pooled_kernel<<<dim3(256, 2, 4), 256>>>(dd[0], dd[1], dd[2], dd[3], dsout);
    token_kernel<<<dim3(1024, 2, 8), 256>>>(Wdsk, bdsk, Wdsv, bdsv, gate);

    for (int lv = 0; lv < 4; lv++) {
        int L = Lt[lv], M = L + 32;
        dim3 grid(L / 64, 4, 2), blk(16, 16);
        gemm256<<<grid, blk>>>(Wq + lv * 65536, bq + lv * 256, sp[lv], nullptr, nullptr,
                               L, M, qoff[lv], 0, 0);
        gemm256<<<grid, blk>>>(Wk + lv * 65536, bk + lv * 256, iv[lv], nullptr, nullptr,
                               L, M, kvoff[lv], 0, 1);
        gemm256<<<grid, blk>>>(Wv + lv * 65536, bv + lv * 256, iv[lv], nullptr, nullptr,
                               L, M, kvoff[lv], 0, 2);
        int gx = (L + 255) / 256; if (gx < 1) gx = 1;
        attn_kernel<<<dim3(gx, HEADS, 2), 256>>>(qoff[lv], kvoff[lv], L, M,
                                                 dsout, 1.0f / (64.0f * (float)L), lv);
    }
    for (int lv = 0; lv < 4; lv++) {
        int L = Lt[lv], M = L + 32;
        dim3 grid(L / 64, 4, 2), blk(16, 16);
        gemm256<<<grid, blk>>>(Wo + lv * 65536, bo + lv * 256, nullptr, sp[lv], out,
                               L, M, qoff[lv], qoff[lv], 3);
    }
}